// round 7
// baseline (speedup 1.0000x reference)
#include <cuda_runtime.h>
#include <cuda_bf16.h>
#include <stdint.h>
#include <math.h>

// ---------------------------------------------------------------------------
// HierarchicalClassifier via warp-level bf16 mma.sync (HMMA) on sm_103a.
//   logits[16384,136] = features[16384,2048] @ Wpacked[2048,136] + bias
//   fp32 emulated: Ah*Bh + Ah*Bl + Al*Bh (bf16 hi/lo split, 3 MMAs).
//   Packed cols: [0,128) bottom (t=n>>4, c=n&15), [128,136) top gate, pad->144.
// R6: 512 threads / 16 warps (warp tile 16x72) -> 4 warps/SMSP for TLP.
// ---------------------------------------------------------------------------

#define D_K   2048
#define N_PAD 144
#define N_REAL 136

__device__ __nv_bfloat16 g_Bh[N_PAD * D_K];   // [n][k] K-major
__device__ __nv_bfloat16 g_Bl[N_PAD * D_K];
__device__ float         g_bias[N_PAD];

// ---------------------------------------------------------------------------
__global__ void pack_kernel(const float* __restrict__ topW,
                            const float* __restrict__ topb,
                            const float* __restrict__ botW,
                            const float* __restrict__ botb) {
    int idx = blockIdx.x * blockDim.x + threadIdx.x;
    if (idx < N_PAD * D_K) {
        int n = idx / D_K, k = idx - n * D_K;
        float v = 0.0f;
        if (n < 128) {
            int t = n >> 4, c = n & 15;
            v = botW[((size_t)t * D_K + k) * 16 + c];
        } else if (n < N_REAL) {
            v = topW[(n - 128) * D_K + k];
        }
        __nv_bfloat16 hi = __float2bfloat16(v);
        g_Bh[idx] = hi;
        g_Bl[idx] = __float2bfloat16(v - __bfloat162float(hi));
    }
    if (idx < N_PAD) {
        float b = 0.0f;
        if (idx < 128)         b = botb[idx];
        else if (idx < N_REAL) b = topb[idx - 128];
        g_bias[idx] = b;
    }
}

// ---------------------------------------------------------------------------
__device__ __forceinline__ uint32_t smem_u32(const void* p) {
    uint32_t a;
    asm("{ .reg .u64 t; cvta.to.shared.u64 t, %1; cvt.u32.u64 %0, t; }"
        : "=r"(a) : "l"(p));
    return a;
}

#define LDSM_X4(r0, r1, r2, r3, addr) \
    asm volatile("ldmatrix.sync.aligned.m8n8.x4.shared.b16 {%0,%1,%2,%3}, [%4];" \
        : "=r"(r0), "=r"(r1), "=r"(r2), "=r"(r3) : "r"(addr))

#define LDSM_X2(r0, r1, addr) \
    asm volatile("ldmatrix.sync.aligned.m8n8.x2.shared.b16 {%0,%1}, [%2];" \
        : "=r"(r0), "=r"(r1) : "r"(addr))

#define MMA_BF16(d, a, b0, b1) \
    asm volatile("mma.sync.aligned.m16n8k16.row.col.f32.bf16.bf16.f32 " \
        "{%0,%1,%2,%3}, {%4,%5,%6,%7}, {%8,%9}, {%0,%1,%2,%3};" \
        : "+f"((d)[0]), "+f"((d)[1]), "+f"((d)[2]), "+f"((d)[3]) \
        : "r"((a)[0]), "r"((a)[1]), "r"((a)[2]), "r"((a)[3]), \
          "r"(b0), "r"(b1))

#define CP16(dst, src) \
    asm volatile("cp.async.cg.shared.global [%0], [%1], 16;" \
        :: "r"(dst), "l"(src) : "memory")
#define CP_COMMIT() asm volatile("cp.async.commit_group;" ::: "memory")
#define CP_WAIT0()  asm volatile("cp.async.wait_group 0;" ::: "memory")

__device__ __forceinline__ void split2(float v0, float v1, uint32_t& h, uint32_t& l) {
    uint32_t hp;
    asm("cvt.rn.bf16x2.f32 %0, %1, %2;" : "=r"(hp) : "f"(v1), "f"(v0));
    float h0 = __uint_as_float(hp << 16);
    float h1 = __uint_as_float(hp & 0xffff0000u);
    uint32_t lp;
    asm("cvt.rn.bf16x2.f32 %0, %1, %2;" : "=r"(lp) : "f"(v1 - h1), "f"(v0 - h0));
    h = hp; l = lp;
}

// ---------------------------------------------------------------------------
// Stage layout (row pitch 144B = 128B data + 16B pad, conflict-free LDSM/STS):
//   Ahi @0 (128*144=18432) | Alo @18432 | Bhi @36864 (144*144=20736) | Blo @57600
// STAGE = 78336, double buffered.
// ---------------------------------------------------------------------------
constexpr int PITCH    = 144;
constexpr int AHI_OFF  = 0;
constexpr int ALO_OFF  = 18432;
constexpr int BHI_OFF  = 36864;
constexpr int BLO_OFF  = 57600;
constexpr int STAGE    = 78336;
constexpr int SMEM_DYN = 2 * STAGE;   // 156672

constexpr int NTHR = 512;

__global__ __launch_bounds__(NTHR, 1)
void hc_mma_kernel(const float* __restrict__ A, float* __restrict__ out) {
    extern __shared__ char sm[];
    const int tid  = threadIdx.x;
    const int wid  = tid >> 5, lane = tid & 31;
    const int row0 = blockIdx.x * 128;
    const uint32_t smu = smem_u32(sm);

    // A loader: row = tid>>2, quarter (16 floats) = tid&3
    const int lr = tid >> 2;
    const int lq = tid & 3;
    const float* aPtr = A + (size_t)(row0 + lr) * D_K + lq * 16;

    // warp tile: 8 M-warps x 2 N-warps; warp computes 16 x 72
    const int m0 = (wid & 7) * 16;
    const int n0 = (wid >> 3) * 72;

    const int frow = lane & 15;
    const int fk   = (lane >> 4) * 8;        // 0 or 8 (elements)
    const int x2row = lane & 7;
    const int x2k   = ((lane >> 3) & 1) * 8;

    float acc[9][4];
    #pragma unroll
    for (int j = 0; j < 9; j++)
        #pragma unroll
        for (int e = 0; e < 4; e++) acc[j][e] = 0.0f;

    float4 av[4];

    auto loadA = [&](int kt) {
        #pragma unroll
        for (int q = 0; q < 4; q++) av[q] = *(const float4*)(aPtr + kt + q * 4);
    };
    auto cpB = [&](int kt, int s) {
        uint32_t bBase = smu + s * STAGE + BHI_OFF;
        #pragma unroll
        for (int p = 0; p < 5; p++) {
            int i = tid + p * NTHR;                // 0..2559, need < 2304
            if (i < 2304) {
                int half = (i >= 1152) ? 1 : 0;
                int j = i - half * 1152;
                int n = j >> 3, seg = j & 7;       // n 0..143, seg 0..7 (16B units)
                const __nv_bfloat16* src =
                    (half ? g_Bl : g_Bh) + (size_t)n * D_K + kt + seg * 8;
                uint32_t dst = bBase + half * 20736 + n * PITCH + seg * 16;
                CP16(dst, src);
            }
        }
    };
    auto stsA = [&](int s) {
        uint32_t hi[8], lo[8];
        #pragma unroll
        for (int q = 0; q < 4; q++) {
            split2(av[q].x, av[q].y, hi[2 * q], lo[2 * q]);
            split2(av[q].z, av[q].w, hi[2 * q + 1], lo[2 * q + 1]);
        }
        char* aB = sm + s * STAGE + lr * PITCH + lq * 32;
        *(uint4*)(aB + AHI_OFF)      = make_uint4(hi[0], hi[1], hi[2], hi[3]);
        *(uint4*)(aB + AHI_OFF + 16) = make_uint4(hi[4], hi[5], hi[6], hi[7]);
        *(uint4*)(aB + ALO_OFF)      = make_uint4(lo[0], lo[1], lo[2], lo[3]);
        *(uint4*)(aB + ALO_OFF + 16) = make_uint4(lo[4], lo[5], lo[6], lo[7]);
    };

    auto compute = [&](int s) {
        uint32_t stg  = smu + s * STAGE;
        uint32_t aHiB = stg + AHI_OFF, aLoB = stg + ALO_OFF;
        uint32_t bHiB = stg + BHI_OFF, bLoB = stg + BLO_OFF;

        #pragma unroll
        for (int ks = 0; ks < 4; ks++) {
            const int kk = ks * 16;
            // A frags (one 16-row m-tile)
            uint32_t ah[4], al[4];
            uint32_t ra = (uint32_t)((m0 + frow) * PITCH + (kk + fk) * 2);
            LDSM_X4(ah[0], ah[1], ah[2], ah[3], aHiB + ra);
            LDSM_X4(al[0], al[1], al[2], al[3], aLoB + ra);

            // 4 full 16-col B groups
            #pragma unroll
            for (int g = 0; g < 4; g++) {
                uint32_t rb = (uint32_t)((n0 + g * 16 + frow) * PITCH + (kk + fk) * 2);
                uint32_t h0, h1, h2, h3, l0, l1, l2, l3;
                LDSM_X4(h0, h1, h2, h3, bHiB + rb);
                LDSM_X4(l0, l1, l2, l3, bLoB + rb);
                MMA_BF16(acc[2*g],   ah, h0, h2);
                MMA_BF16(acc[2*g+1], ah, h1, h3);
                MMA_BF16(acc[2*g],   ah, l0, l2);
                MMA_BF16(acc[2*g+1], ah, l1, l3);
                MMA_BF16(acc[2*g],   al, h0, h2);
                MMA_BF16(acc[2*g+1], al, h1, h3);
            }
            // trailing 8-col group via ldmatrix.x2
            {
                uint32_t rbx = (uint32_t)((n0 + 64 + x2row) * PITCH + (kk + x2k) * 2);
                uint32_t xh0, xh1, xl0, xl1;
                LDSM_X2(xh0, xh1, bHiB + rbx);
                LDSM_X2(xl0, xl1, bLoB + rbx);
                MMA_BF16(acc[8], ah, xh0, xh1);
                MMA_BF16(acc[8], ah, xl0, xl1);
                MMA_BF16(acc[8], al, xh0, xh1);
            }
        }
    };

    // ---- pipeline: 32 chunks of BK=64 ----
    loadA(0);
    cpB(0, 0);
    CP_COMMIT();
    stsA(0);
    CP_WAIT0();
    __syncthreads();

    for (int ck = 0; ck < 32; ck++) {
        int s = ck & 1;
        if (ck < 31) {
            loadA((ck + 1) * 64);
            cpB((ck + 1) * 64, s ^ 1);
            CP_COMMIT();
        }
        compute(s);
        if (ck < 31) {
            stsA(s ^ 1);
            CP_WAIT0();
            __syncthreads();
        }
    }
    __syncthreads();

    // ---- stage logits (+bias) into SMEM, [128][144] f32 ----
    float* Ls = (float*)sm;
    {
        const int rr = lane >> 2;
        const int cc = (lane & 3) * 2;
        #pragma unroll
        for (int j = 0; j < 9; j++) {
            int r = m0 + rr;
            int c = n0 + j * 8 + cc;
            float b0 = g_bias[c], b1 = g_bias[c + 1];
            Ls[r * N_PAD + c]           = acc[j][0] + b0;
            Ls[r * N_PAD + c + 1]       = acc[j][1] + b1;
            Ls[(r + 8) * N_PAD + c]     = acc[j][2] + b0;
            Ls[(r + 8) * N_PAD + c + 1] = acc[j][3] + b1;
        }
    }
    __syncthreads();

    // ---- epilogue: 128 rows x 8 top-labels = 1024 tasks, 2/thread ----
    #pragma unroll
    for (int p = 0; p < 2; p++) {
        int task = tid + p * NTHR;
        int r = task >> 3, t = task & 7;
        const float* Lr = Ls + r * N_PAD;

        float gate = 1.0f / (1.0f + __expf(-Lr[128 + t]));

        float l[16], mx = -1e30f;
        #pragma unroll
        for (int c = 0; c < 16; c++) {
            l[c] = Lr[t * 16 + c];
            mx = fmaxf(mx, l[c]);
        }
        float ssum = 0.0f;
        #pragma unroll
        for (int c = 0; c < 16; c++) { l[c] = __expf(l[c] - mx); ssum += l[c]; }
        float sc = gate / ssum;

        float* op = out + (size_t)(row0 + r) * 128 + t * 16;
        #pragma unroll
        for (int q = 0; q < 4; q++) {
            float4 v;
            v.x = l[q * 4 + 0] * sc;
            v.y = l[q * 4 + 1] * sc;
            v.z = l[q * 4 + 2] * sc;
            v.w = l[q * 4 + 3] * sc;
            ((float4*)op)[q] = v;
        }
    }
}

// ---------------------------------------------------------------------------
extern "C" void kernel_launch(void* const* d_in, const int* in_sizes, int n_in,
                              void* d_out, int out_size) {
    const float* features = (const float*)d_in[0];
    const float* topW     = (const float*)d_in[1];
    const float* topb     = (const float*)d_in[2];
    const float* botW     = (const float*)d_in[3];
    const float* botb     = (const float*)d_in[4];
    float* out = (float*)d_out;

    cudaFuncSetAttribute(hc_mma_kernel,
                         cudaFuncAttributeMaxDynamicSharedMemorySize, SMEM_DYN);

    pack_kernel<<<(N_PAD * D_K + 255) / 256, 256>>>(topW, topb, botW, botb);
    hc_mma_kernel<<<16384 / 128, NTHR, SMEM_DYN>>>(features, out);
}

// round 8
// speedup vs baseline: 1.0918x; 1.0918x over previous
#include <cuda_runtime.h>
#include <cuda_bf16.h>
#include <stdint.h>
#include <math.h>

// ---------------------------------------------------------------------------
// HierarchicalClassifier via warp-level bf16 mma.sync (HMMA) on sm_103a.
//   logits[16384,136] = features[16384,2048] @ Wpacked[2048,136] + bias
//   fp32 emulated: Ah*Bh + Ah*Bl + Al*Bh (bf16 hi/lo split, 3 MMAs).
//   Packed cols: [0,128) bottom (t=n>>4, c=n&15), [128,136) top gate, pad->144.
// R7: 12 warps as 4Mx3N (warp tile 32x48, clean 16-col groups, no x2 tail).
//     Minimizes SMEM crossbar traffic (Wm*B + Wn*A) at 3 warps/SMSP.
// ---------------------------------------------------------------------------

#define D_K   2048
#define N_PAD 144
#define N_REAL 136

__device__ __nv_bfloat16 g_Bh[N_PAD * D_K];   // [n][k] K-major
__device__ __nv_bfloat16 g_Bl[N_PAD * D_K];
__device__ float         g_bias[N_PAD];

// ---------------------------------------------------------------------------
__global__ void pack_kernel(const float* __restrict__ topW,
                            const float* __restrict__ topb,
                            const float* __restrict__ botW,
                            const float* __restrict__ botb) {
    int idx = blockIdx.x * blockDim.x + threadIdx.x;
    if (idx < N_PAD * D_K) {
        int n = idx / D_K, k = idx - n * D_K;
        float v = 0.0f;
        if (n < 128) {
            int t = n >> 4, c = n & 15;
            v = botW[((size_t)t * D_K + k) * 16 + c];
        } else if (n < N_REAL) {
            v = topW[(n - 128) * D_K + k];
        }
        __nv_bfloat16 hi = __float2bfloat16(v);
        g_Bh[idx] = hi;
        g_Bl[idx] = __float2bfloat16(v - __bfloat162float(hi));
    }
    if (idx < N_PAD) {
        float b = 0.0f;
        if (idx < 128)         b = botb[idx];
        else if (idx < N_REAL) b = topb[idx - 128];
        g_bias[idx] = b;
    }
}

// ---------------------------------------------------------------------------
__device__ __forceinline__ uint32_t smem_u32(const void* p) {
    uint32_t a;
    asm("{ .reg .u64 t; cvta.to.shared.u64 t, %1; cvt.u32.u64 %0, t; }"
        : "=r"(a) : "l"(p));
    return a;
}

#define LDSM_X4(r0, r1, r2, r3, addr) \
    asm volatile("ldmatrix.sync.aligned.m8n8.x4.shared.b16 {%0,%1,%2,%3}, [%4];" \
        : "=r"(r0), "=r"(r1), "=r"(r2), "=r"(r3) : "r"(addr))

#define MMA_BF16(d, a, b0, b1) \
    asm volatile("mma.sync.aligned.m16n8k16.row.col.f32.bf16.bf16.f32 " \
        "{%0,%1,%2,%3}, {%4,%5,%6,%7}, {%8,%9}, {%0,%1,%2,%3};" \
        : "+f"((d)[0]), "+f"((d)[1]), "+f"((d)[2]), "+f"((d)[3]) \
        : "r"((a)[0]), "r"((a)[1]), "r"((a)[2]), "r"((a)[3]), \
          "r"(b0), "r"(b1))

#define CP16(dst, src) \
    asm volatile("cp.async.cg.shared.global [%0], [%1], 16;" \
        :: "r"(dst), "l"(src) : "memory")
#define CP_COMMIT() asm volatile("cp.async.commit_group;" ::: "memory")
#define CP_WAIT0()  asm volatile("cp.async.wait_group 0;" ::: "memory")

__device__ __forceinline__ void split2(float v0, float v1, uint32_t& h, uint32_t& l) {
    uint32_t hp;
    asm("cvt.rn.bf16x2.f32 %0, %1, %2;" : "=r"(hp) : "f"(v1), "f"(v0));
    float h0 = __uint_as_float(hp << 16);
    float h1 = __uint_as_float(hp & 0xffff0000u);
    uint32_t lp;
    asm("cvt.rn.bf16x2.f32 %0, %1, %2;" : "=r"(lp) : "f"(v1 - h1), "f"(v0 - h0));
    h = hp; l = lp;
}

// ---------------------------------------------------------------------------
// Stage layout (row pitch 144B = 128B data + 16B pad, conflict-free LDSM/STS):
//   Ahi @0 (128*144=18432) | Alo @18432 | Bhi @36864 (144*144=20736) | Blo @57600
// STAGE = 78336, double buffered.
// ---------------------------------------------------------------------------
constexpr int PITCH    = 144;
constexpr int AHI_OFF  = 0;
constexpr int ALO_OFF  = 18432;
constexpr int BHI_OFF  = 36864;
constexpr int BLO_OFF  = 57600;
constexpr int STAGE    = 78336;
constexpr int SMEM_DYN = 2 * STAGE;   // 156672

constexpr int NTHR = 384;             // 12 warps: 4 M x 3 N

__global__ __launch_bounds__(NTHR, 1)
void hc_mma_kernel(const float* __restrict__ A, float* __restrict__ out) {
    extern __shared__ char sm[];
    const int tid  = threadIdx.x;
    const int wid  = tid >> 5, lane = tid & 31;
    const int row0 = blockIdx.x * 128;
    const uint32_t smu = smem_u32(sm);

    // warp tile: 4 M-warps x 3 N-warps; warp computes 32 x 48
    const int m0 = (wid & 3) * 32;
    const int n0 = (wid >> 2) * 48;

    const int frow = lane & 15;
    const int fk   = (lane >> 4) * 8;        // 0 or 8 (elements)

    float acc[2][6][4];
    #pragma unroll
    for (int mt = 0; mt < 2; mt++)
        #pragma unroll
        for (int j = 0; j < 6; j++)
            #pragma unroll
            for (int e = 0; e < 4; e++) acc[mt][j][e] = 0.0f;

    // A loader: 512 quarter-row units (row = u>>2, 16 floats = u&3), 2 passes
    float4 av[2][4];

    auto loadA = [&](int kt) {
        #pragma unroll
        for (int p = 0; p < 2; p++) {
            int u = tid + p * NTHR;
            if (u < 512) {
                int row = u >> 2, q = u & 3;
                const float* src = A + (size_t)(row0 + row) * D_K + kt + q * 16;
                #pragma unroll
                for (int x = 0; x < 4; x++) av[p][x] = *(const float4*)(src + x * 4);
            }
        }
    };
    auto cpB = [&](int kt, int s) {
        uint32_t bBase = smu + s * STAGE + BHI_OFF;
        #pragma unroll
        for (int p = 0; p < 6; p++) {
            int i = tid + p * NTHR;                // 0..2303 exactly
            int half = (i >= 1152) ? 1 : 0;
            int j = i - half * 1152;
            int n = j >> 3, seg = j & 7;           // n 0..143, seg 0..7 (16B units)
            const __nv_bfloat16* src =
                (half ? g_Bl : g_Bh) + (size_t)n * D_K + kt + seg * 8;
            uint32_t dst = bBase + half * 20736 + n * PITCH + seg * 16;
            CP16(dst, src);
        }
    };
    auto stsA = [&](int s) {
        #pragma unroll
        for (int p = 0; p < 2; p++) {
            int u = tid + p * NTHR;
            if (u < 512) {
                int row = u >> 2, q = u & 3;
                uint32_t hi[8], lo[8];
                #pragma unroll
                for (int x = 0; x < 4; x++) {
                    split2(av[p][x].x, av[p][x].y, hi[2 * x], lo[2 * x]);
                    split2(av[p][x].z, av[p][x].w, hi[2 * x + 1], lo[2 * x + 1]);
                }
                char* aB = sm + s * STAGE + row * PITCH + q * 32;
                *(uint4*)(aB + AHI_OFF)      = make_uint4(hi[0], hi[1], hi[2], hi[3]);
                *(uint4*)(aB + AHI_OFF + 16) = make_uint4(hi[4], hi[5], hi[6], hi[7]);
                *(uint4*)(aB + ALO_OFF)      = make_uint4(lo[0], lo[1], lo[2], lo[3]);
                *(uint4*)(aB + ALO_OFF + 16) = make_uint4(lo[4], lo[5], lo[6], lo[7]);
            }
        }
    };

    auto compute = [&](int s) {
        uint32_t stg  = smu + s * STAGE;
        uint32_t aHiB = stg + AHI_OFF, aLoB = stg + ALO_OFF;
        uint32_t bHiB = stg + BHI_OFF, bLoB = stg + BLO_OFF;

        #pragma unroll
        for (int ks = 0; ks < 4; ks++) {
            const int kk = ks * 16;
            uint32_t ah[2][4], al[2][4];
            #pragma unroll
            for (int mt = 0; mt < 2; mt++) {
                uint32_t ra = (uint32_t)((m0 + mt * 16 + frow) * PITCH + (kk + fk) * 2);
                LDSM_X4(ah[mt][0], ah[mt][1], ah[mt][2], ah[mt][3], aHiB + ra);
                LDSM_X4(al[mt][0], al[mt][1], al[mt][2], al[mt][3], aLoB + ra);
            }
            // 3 clean 16-col B groups
            #pragma unroll
            for (int g = 0; g < 3; g++) {
                uint32_t rb = (uint32_t)((n0 + g * 16 + frow) * PITCH + (kk + fk) * 2);
                uint32_t h0, h1, h2, h3, l0, l1, l2, l3;
                LDSM_X4(h0, h1, h2, h3, bHiB + rb);
                LDSM_X4(l0, l1, l2, l3, bLoB + rb);
                #pragma unroll
                for (int mt = 0; mt < 2; mt++) {
                    MMA_BF16(acc[mt][2*g],   ah[mt], h0, h2);
                    MMA_BF16(acc[mt][2*g+1], ah[mt], h1, h3);
                    MMA_BF16(acc[mt][2*g],   ah[mt], l0, l2);
                    MMA_BF16(acc[mt][2*g+1], ah[mt], l1, l3);
                    MMA_BF16(acc[mt][2*g],   al[mt], h0, h2);
                    MMA_BF16(acc[mt][2*g+1], al[mt], h1, h3);
                }
            }
        }
    };

    // ---- pipeline: 32 chunks of BK=64 ----
    loadA(0);
    cpB(0, 0);
    CP_COMMIT();
    stsA(0);
    CP_WAIT0();
    __syncthreads();

    for (int ck = 0; ck < 32; ck++) {
        int s = ck & 1;
        if (ck < 31) {
            loadA((ck + 1) * 64);
            cpB((ck + 1) * 64, s ^ 1);
            CP_COMMIT();
        }
        compute(s);
        if (ck < 31) {
            stsA(s ^ 1);
            CP_WAIT0();
            __syncthreads();
        }
    }
    __syncthreads();

    // ---- stage logits (+bias) into SMEM, [128][144] f32 ----
    float* Ls = (float*)sm;
    {
        const int rr = lane >> 2;
        const int cc = (lane & 3) * 2;
        #pragma unroll
        for (int mt = 0; mt < 2; mt++)
            #pragma unroll
            for (int j = 0; j < 6; j++) {
                int r = m0 + mt * 16 + rr;
                int c = n0 + j * 8 + cc;
                float b0 = g_bias[c], b1 = g_bias[c + 1];
                Ls[r * N_PAD + c]           = acc[mt][j][0] + b0;
                Ls[r * N_PAD + c + 1]       = acc[mt][j][1] + b1;
                Ls[(r + 8) * N_PAD + c]     = acc[mt][j][2] + b0;
                Ls[(r + 8) * N_PAD + c + 1] = acc[mt][j][3] + b1;
            }
    }
    __syncthreads();

    // ---- epilogue: 128 rows x 8 top-labels = 1024 tasks ----
    #pragma unroll
    for (int p = 0; p < 3; p++) {
        int task = tid + p * NTHR;
        if (task < 1024) {
            int r = task >> 3, t = task & 7;
            const float* Lr = Ls + r * N_PAD;

            float gate = 1.0f / (1.0f + __expf(-Lr[128 + t]));

            float l[16], mx = -1e30f;
            #pragma unroll
            for (int c = 0; c < 16; c++) {
                l[c] = Lr[t * 16 + c];
                mx = fmaxf(mx, l[c]);
            }
            float ssum = 0.0f;
            #pragma unroll
            for (int c = 0; c < 16; c++) { l[c] = __expf(l[c] - mx); ssum += l[c]; }
            float sc = gate / ssum;

            float* op = out + (size_t)(row0 + r) * 128 + t * 16;
            #pragma unroll
            for (int q = 0; q < 4; q++) {
                float4 v;
                v.x = l[q * 4 + 0] * sc;
                v.y = l[q * 4 + 1] * sc;
                v.z = l[q * 4 + 2] * sc;
                v.w = l[q * 4 + 3] * sc;
                ((float4*)op)[q] = v;
            }
        }
    }
}

// ---------------------------------------------------------------------------
extern "C" void kernel_launch(void* const* d_in, const int* in_sizes, int n_in,
                              void* d_out, int out_size) {
    const float* features = (const float*)d_in[0];
    const float* topW     = (const float*)d_in[1];
    const float* topb     = (const float*)d_in[2];
    const float* botW     = (const float*)d_in[3];
    const float* botb     = (const float*)d_in[4];
    float* out = (float*)d_out;

    cudaFuncSetAttribute(hc_mma_kernel,
                         cudaFuncAttributeMaxDynamicSharedMemorySize, SMEM_DYN);

    pack_kernel<<<(N_PAD * D_K + 255) / 256, 256>>>(topW, topb, botW, botb);
    hc_mma_kernel<<<16384 / 128, NTHR, SMEM_DYN>>>(features, out);
}

// round 10
// speedup vs baseline: 1.1171x; 1.0232x over previous
#include <cuda_runtime.h>
#include <cuda_bf16.h>
#include <stdint.h>
#include <math.h>

// ---------------------------------------------------------------------------
// HierarchicalClassifier via warp-level bf16 mma.sync (HMMA) on sm_103a.
//   logits[16384,136] = features[16384,2048] @ Wpacked[2048,136] + bias
//   fp32 emulated: Ah*Bh + Ah*Bl + Al*Bh (bf16 hi/lo split, 3 MMAs).
//   Packed cols: [0,128) bottom (t=n>>4, c=n&15), [128,136) top gate, pad->144.
// R8: warp specialization. 4 producer warps (LDG/split/STS/cp.async) + 12
//     consumer warps (pure LDSM+MMA, 4Mx3N, 32x48 tile). Named-barrier
//     producer/consumer handshake so fill (crossbar) overlaps MMA (tensor).
// ---------------------------------------------------------------------------

#define D_K   2048
#define N_PAD 144
#define N_REAL 136

__device__ __nv_bfloat16 g_Bh[N_PAD * D_K];   // [n][k] K-major
__device__ __nv_bfloat16 g_Bl[N_PAD * D_K];
__device__ float         g_bias[N_PAD];

// ---------------------------------------------------------------------------
__global__ void pack_kernel(const float* __restrict__ topW,
                            const float* __restrict__ topb,
                            const float* __restrict__ botW,
                            const float* __restrict__ botb) {
    int idx = blockIdx.x * blockDim.x + threadIdx.x;
    if (idx < N_PAD * D_K) {
        int n = idx / D_K, k = idx - n * D_K;
        float v = 0.0f;
        if (n < 128) {
            int t = n >> 4, c = n & 15;
            v = botW[((size_t)t * D_K + k) * 16 + c];
        } else if (n < N_REAL) {
            v = topW[(n - 128) * D_K + k];
        }
        __nv_bfloat16 hi = __float2bfloat16(v);
        g_Bh[idx] = hi;
        g_Bl[idx] = __float2bfloat16(v - __bfloat162float(hi));
    }
    if (idx < N_PAD) {
        float b = 0.0f;
        if (idx < 128)         b = botb[idx];
        else if (idx < N_REAL) b = topb[idx - 128];
        g_bias[idx] = b;
    }
}

// ---------------------------------------------------------------------------
__device__ __forceinline__ uint32_t smem_u32(const void* p) {
    uint32_t a;
    asm("{ .reg .u64 t; cvta.to.shared.u64 t, %1; cvt.u32.u64 %0, t; }"
        : "=r"(a) : "l"(p));
    return a;
}

#define LDSM_X4(r0, r1, r2, r3, addr) \
    asm volatile("ldmatrix.sync.aligned.m8n8.x4.shared.b16 {%0,%1,%2,%3}, [%4];" \
        : "=r"(r0), "=r"(r1), "=r"(r2), "=r"(r3) : "r"(addr))

#define MMA_BF16(d, a, b0, b1) \
    asm volatile("mma.sync.aligned.m16n8k16.row.col.f32.bf16.bf16.f32 " \
        "{%0,%1,%2,%3}, {%4,%5,%6,%7}, {%8,%9}, {%0,%1,%2,%3};" \
        : "+f"((d)[0]), "+f"((d)[1]), "+f"((d)[2]), "+f"((d)[3]) \
        : "r"((a)[0]), "r"((a)[1]), "r"((a)[2]), "r"((a)[3]), \
          "r"(b0), "r"(b1))

#define CP16(dst, src) \
    asm volatile("cp.async.cg.shared.global [%0], [%1], 16;" \
        :: "r"(dst), "l"(src) : "memory")
#define CP_COMMIT() asm volatile("cp.async.commit_group;" ::: "memory")
#define CP_WAIT0()  asm volatile("cp.async.wait_group 0;" ::: "memory")

#define BAR_SYNC(id)   asm volatile("bar.sync %0, 512;"   :: "r"(id) : "memory")
#define BAR_ARRIVE(id) asm volatile("bar.arrive %0, 512;" :: "r"(id) : "memory")

__device__ __forceinline__ void split2(float v0, float v1, uint32_t& h, uint32_t& l) {
    uint32_t hp;
    asm("cvt.rn.bf16x2.f32 %0, %1, %2;" : "=r"(hp) : "f"(v1), "f"(v0));
    float h0 = __uint_as_float(hp << 16);
    float h1 = __uint_as_float(hp & 0xffff0000u);
    uint32_t lp;
    asm("cvt.rn.bf16x2.f32 %0, %1, %2;" : "=r"(lp) : "f"(v1 - h1), "f"(v0 - h0));
    h = hp; l = lp;
}

// ---------------------------------------------------------------------------
// Stage layout (row pitch 144B = 128B data + 16B pad, conflict-free LDSM/STS):
//   Ahi @0 (128*144=18432) | Alo @18432 | Bhi @36864 (144*144=20736) | Blo @57600
// STAGE = 78336, double buffered.
// ---------------------------------------------------------------------------
constexpr int PITCH    = 144;
constexpr int AHI_OFF  = 0;
constexpr int ALO_OFF  = 18432;
constexpr int BHI_OFF  = 36864;
constexpr int BLO_OFF  = 57600;
constexpr int STAGE    = 78336;
constexpr int SMEM_DYN = 2 * STAGE;   // 156672

constexpr int NTHR   = 512;           // 12 consumer warps + 4 producer warps
constexpr int NCONS  = 12;            // consumer warps: 4 M x 3 N

// named barrier ids: FULL(s) = 1+s (producer->consumer), FREE(s) = 3+s
#define FULL_BAR(s) (1 + (s))
#define FREE_BAR(s) (3 + (s))

__global__ __launch_bounds__(NTHR, 1)
void hc_mma_kernel(const float* __restrict__ A, float* __restrict__ out) {
    extern __shared__ char sm[];
    const int tid  = threadIdx.x;
    const int wid  = tid >> 5, lane = tid & 31;
    const int row0 = blockIdx.x * 128;
    const uint32_t smu = smem_u32(sm);

    if (wid < NCONS) {
        // =============================== CONSUMER ===========================
        const int m0 = (wid & 3) * 32;
        const int n0 = (wid >> 2) * 48;
        const int frow = lane & 15;
        const int fk   = (lane >> 4) * 8;

        float acc[2][6][4];
        #pragma unroll
        for (int mt = 0; mt < 2; mt++)
            #pragma unroll
            for (int j = 0; j < 6; j++)
                #pragma unroll
                for (int e = 0; e < 4; e++) acc[mt][j][e] = 0.0f;

        for (int ck = 0; ck < 32; ck++) {
            const int s = ck & 1;
            BAR_SYNC(FULL_BAR(s));

            uint32_t stg  = smu + s * STAGE;
            uint32_t aHiB = stg + AHI_OFF, aLoB = stg + ALO_OFF;
            uint32_t bHiB = stg + BHI_OFF, bLoB = stg + BLO_OFF;

            #pragma unroll
            for (int ks = 0; ks < 4; ks++) {
                const int kk = ks * 16;
                uint32_t ah[2][4], al[2][4];
                #pragma unroll
                for (int mt = 0; mt < 2; mt++) {
                    uint32_t ra = (uint32_t)((m0 + mt * 16 + frow) * PITCH + (kk + fk) * 2);
                    LDSM_X4(ah[mt][0], ah[mt][1], ah[mt][2], ah[mt][3], aHiB + ra);
                    LDSM_X4(al[mt][0], al[mt][1], al[mt][2], al[mt][3], aLoB + ra);
                }
                #pragma unroll
                for (int g = 0; g < 3; g++) {
                    uint32_t rb = (uint32_t)((n0 + g * 16 + frow) * PITCH + (kk + fk) * 2);
                    uint32_t h0, h1, h2, h3, l0, l1, l2, l3;
                    LDSM_X4(h0, h1, h2, h3, bHiB + rb);
                    LDSM_X4(l0, l1, l2, l3, bLoB + rb);
                    #pragma unroll
                    for (int mt = 0; mt < 2; mt++) {
                        MMA_BF16(acc[mt][2*g],   ah[mt], h0, h2);
                        MMA_BF16(acc[mt][2*g+1], ah[mt], h1, h3);
                        MMA_BF16(acc[mt][2*g],   ah[mt], l0, l2);
                        MMA_BF16(acc[mt][2*g+1], ah[mt], l1, l3);
                        MMA_BF16(acc[mt][2*g],   al[mt], h0, h2);
                        MMA_BF16(acc[mt][2*g+1], al[mt], h1, h3);
                    }
                }
            }
            BAR_ARRIVE(FREE_BAR(s));
        }

        // stage logits (+bias) into stage-0 SMEM region [128][144] f32
        float* Ls = (float*)sm;
        const int rr = lane >> 2;
        const int cc = (lane & 3) * 2;
        #pragma unroll
        for (int mt = 0; mt < 2; mt++)
            #pragma unroll
            for (int j = 0; j < 6; j++) {
                int r = m0 + mt * 16 + rr;
                int c = n0 + j * 8 + cc;
                float b0 = g_bias[c], b1 = g_bias[c + 1];
                Ls[r * N_PAD + c]           = acc[mt][j][0] + b0;
                Ls[r * N_PAD + c + 1]       = acc[mt][j][1] + b1;
                Ls[(r + 8) * N_PAD + c]     = acc[mt][j][2] + b0;
                Ls[(r + 8) * N_PAD + c + 1] = acc[mt][j][3] + b1;
            }
    } else {
        // =============================== PRODUCER ===========================
        const int tp = tid - NCONS * 32;          // 0..127
        const float* aRow = A + (size_t)(row0 + tp) * D_K;
        char* aDst = sm + tp * PITCH;

        float4 av[16];
        auto ldgA = [&](int kt) {
            #pragma unroll
            for (int q = 0; q < 16; q++)
                av[q] = *(const float4*)(aRow + kt + q * 4);
        };
        auto cpB = [&](int kt, int s) {
            uint32_t bBase = smu + s * STAGE + BHI_OFF;
            #pragma unroll
            for (int p = 0; p < 18; p++) {
                int i = tp + p * 128;               // 0..2303 exactly
                int half = (i >= 1152) ? 1 : 0;
                int j = i - half * 1152;
                int n = j >> 3, seg = j & 7;
                const __nv_bfloat16* src =
                    (half ? g_Bl : g_Bh) + (size_t)n * D_K + kt + seg * 8;
                uint32_t dst = bBase + half * 20736 + n * PITCH + seg * 16;
                CP16(dst, src);
            }
        };
        auto stsA = [&](int s) {
            char* d = aDst + s * STAGE;
            #pragma unroll
            for (int q = 0; q < 4; q++) {
                uint32_t hi[8], lo[8];
                #pragma unroll
                for (int x = 0; x < 4; x++) {
                    split2(av[4*q+x].x, av[4*q+x].y, hi[2*x],   lo[2*x]);
                    split2(av[4*q+x].z, av[4*q+x].w, hi[2*x+1], lo[2*x+1]);
                }
                *(uint4*)(d + AHI_OFF + q * 32)      = make_uint4(hi[0], hi[1], hi[2], hi[3]);
                *(uint4*)(d + AHI_OFF + q * 32 + 16) = make_uint4(hi[4], hi[5], hi[6], hi[7]);
                *(uint4*)(d + ALO_OFF + q * 32)      = make_uint4(lo[0], lo[1], lo[2], lo[3]);
                *(uint4*)(d + ALO_OFF + q * 32 + 16) = make_uint4(lo[4], lo[5], lo[6], lo[7]);
            }
        };

        // prologue: fill both buffers
        ldgA(0);
        cpB(0, 0);
        stsA(0);
        CP_COMMIT();
        CP_WAIT0();
        BAR_ARRIVE(FULL_BAR(0));

        ldgA(64);
        cpB(64, 1);
        stsA(1);
        CP_COMMIT();
        CP_WAIT0();
        BAR_ARRIVE(FULL_BAR(1));

        for (int ck = 2; ck < 32; ck++) {
            const int s = ck & 1;
            ldgA(ck * 64);                 // LDG in flight across the FREE wait
            BAR_SYNC(FREE_BAR(s));
            cpB(ck * 64, s);
            stsA(s);
            CP_COMMIT();
            CP_WAIT0();
            BAR_ARRIVE(FULL_BAR(s));
        }
    }

    __syncthreads();

    // ---- epilogue: 128 rows x 8 top-labels = 1024 tasks, 2/thread ----
    const float* Ls = (const float*)sm;
    #pragma unroll
    for (int p = 0; p < 2; p++) {
        int task = tid + p * NTHR;
        int r = task >> 3, t = task & 7;
        const float* Lr = Ls + r * N_PAD;

        float gate = 1.0f / (1.0f + __expf(-Lr[128 + t]));

        float l[16], mx = -1e30f;
        #pragma unroll
        for (int c = 0; c < 16; c++) {
            l[c] = Lr[t * 16 + c];
            mx = fmaxf(mx, l[c]);
        }
        float ssum = 0.0f;
        #pragma unroll
        for (int c = 0; c < 16; c++) { l[c] = __expf(l[c] - mx); ssum += l[c]; }
        float sc = gate / ssum;

        float* op = out + (size_t)(row0 + r) * 128 + t * 16;
        #pragma unroll
        for (int q = 0; q < 4; q++) {
            float4 v;
            v.x = l[q * 4 + 0] * sc;
            v.y = l[q * 4 + 1] * sc;
            v.z = l[q * 4 + 2] * sc;
            v.w = l[q * 4 + 3] * sc;
            ((float4*)op)[q] = v;
        }
    }
}

// ---------------------------------------------------------------------------
extern "C" void kernel_launch(void* const* d_in, const int* in_sizes, int n_in,
                              void* d_out, int out_size) {
    const float* features = (const float*)d_in[0];
    const float* topW     = (const float*)d_in[1];
    const float* topb     = (const float*)d_in[2];
    const float* botW     = (const float*)d_in[3];
    const float* botb     = (const float*)d_in[4];
    float* out = (float*)d_out;

    cudaFuncSetAttribute(hc_mma_kernel,
                         cudaFuncAttributeMaxDynamicSharedMemorySize, SMEM_DYN);

    pack_kernel<<<(N_PAD * D_K + 255) / 256, 256>>>(topW, topb, botW, botb);
    hc_mma_kernel<<<16384 / 128, NTHR, SMEM_DYN>>>(features, out);
}